// round 7
// baseline (speedup 1.0000x reference)
#include <cuda_runtime.h>

// RecurrentGCN_87926570483780
//
// Reference math collapses exactly:
//   - K=1 DConv: edge data is dead code.
//   - H0 = zeros -> Z,R depend only on X; cell = (1-Z)*Ht.
//   - Final op: log_softmax over a size-1 axis == 0 identically.
// Output is EXACTLY zeros([N,1]) for all inputs -> one zero-fill node.
//
// Converged configuration (session minimum, 4.51us):
//   123 blocks x 256 threads, 2 predicated STG.128 per thread.
// Explored & rejected: memset node (7.1us), 1024-thr blocks (6.9us),
// 62-block grid-stride (4.58us, tie/noise), 245-block 1-store (4.86us).
// Remaining time is fixed graph-node replay + kernel launch ramp
// (issue <6%, DRAM 0% -> no memory or compute bottleneck exists).

__global__ void __launch_bounds__(256) zero_fill_wave(float4* __restrict__ out4, int n4) {
    int base = (blockIdx.x * blockDim.x + threadIdx.x) * 2;
    const float4 z = make_float4(0.f, 0.f, 0.f, 0.f);
    if (base + 1 < n4) {
        out4[base]     = z;
        out4[base + 1] = z;
    } else if (base < n4) {
        out4[base] = z;
    }
}

extern "C" void kernel_launch(void* const* d_in, const int* in_sizes, int n_in,
                              void* d_out, int out_size) {
    (void)d_in; (void)in_sizes; (void)n_in;

    int n4 = out_size >> 2;                         // 62500 (out_size % 4 == 0)
    int threads = 256;
    int per_block = threads * 2;                    // float4 slots per block
    int blocks = (n4 + per_block - 1) / per_block;  // 123 -> single cheap wave
    zero_fill_wave<<<blocks, threads>>>((float4*)d_out, n4);
}